// round 3
// baseline (speedup 1.0000x reference)
#include <cuda_runtime.h>
#include <math.h>

// Problem constants
#define BSZ 128
#define TT  512
#define TS  511          // steps = T-1
#define NA  8
#define IND 256          // NA*OD
#define HID 512
#define NCTA 128
#define NTHR 256

typedef unsigned long long ull;

// ---------------- device scratch (no allocations allowed) ----------------
__device__ float g_x[BSZ * HID];          // relu(W1 @ mixed)
__device__ float g_hbuf[2 * BSZ * HID];   // ping-pong h
__device__ float g_c[BSZ * HID];          // cell state (in-place, CTA-owned slices)
__device__ float g_mixed[BSZ * IND];      // teacher-forced input for next step
__device__ float g_lp[BSZ * 256];         // per-thread loss partials (written once at end)
__device__ unsigned g_cnt;                // grid barrier counter (monotonic per launch)
__device__ int g_kfmt;                    // comm_keep storage format: 0=i32,1=f32,2=u8

// ---------------- f32x2 helpers ----------------
__device__ __forceinline__ ull pk2(float lo, float hi) {
    ull r; asm("mov.b64 %0, {%1, %2};" : "=l"(r) : "f"(lo), "f"(hi)); return r;
}
__device__ __forceinline__ void upk2(ull v, float& lo, float& hi) {
    asm("mov.b64 {%0, %1}, %2;" : "=f"(lo), "=f"(hi) : "l"(v));
}
__device__ __forceinline__ void fma2(ull& acc, ull a, ull b) {
    asm("fma.rn.f32x2 %0, %1, %2, %0;" : "+l"(acc) : "l"(a), "l"(b));
}
__device__ __forceinline__ float sigf(float x) { return 1.0f / (1.0f + expf(-x)); }

__device__ __forceinline__ bool keep_at(const void* keep, int fmt, int step, int b, int na) {
    long idx = ((long)step * BSZ + b) * NA + na;
    if (fmt == 0) return ((const int*)keep)[idx] != 0;
    if (fmt == 1) return ((const float*)keep)[idx] != 0.0f;
    return ((const unsigned char*)keep)[idx] != 0;
}

// ---------------- grid barrier (monotonic counter; reset by CTA0 at kernel end) ----
__device__ __forceinline__ void gridbar(unsigned& tgt) {
    tgt += NCTA;
    __syncthreads();
    if (threadIdx.x == 0) {
        __threadfence();
        atomicAdd(&g_cnt, 1u);
        while (*(volatile unsigned*)&g_cnt < tgt) { }
        __threadfence();
    }
    __syncthreads();
}

// ---------------- staging helpers: 64 rows x 32 k chunk, transposed to [k][row] ----
#define PF(P0, P1, SRC, RS, CB) do {                                             \
    int _l0 = tid, _l1 = tid + 256;                                              \
    P0 = *(const float4*)&(SRC)[(m0 + (_l0 >> 3)) * (RS) + (CB) + ((_l0 & 7) << 2)]; \
    P1 = *(const float4*)&(SRC)[(m0 + (_l1 >> 3)) * (RS) + (CB) + ((_l1 & 7) << 2)]; \
} while (0)

#define STG(BUF, P0, P1) do {                                                    \
    int _l0 = tid, _l1 = tid + 256;                                              \
    float* _d0 = &(BUF)[((_l0 & 7) << 2) * 68 + (_l0 >> 3)];                     \
    _d0[0] = P0.x; _d0[68] = P0.y; _d0[136] = P0.z; _d0[204] = P0.w;             \
    float* _d1 = &(BUF)[((_l1 & 7) << 2) * 68 + (_l1 >> 3)];                     \
    _d1[0] = P1.x; _d1[68] = P1.y; _d1[136] = P1.z; _d1[204] = P1.w;             \
} while (0)

// SMEM layout (floats)
#define OFF_WIH  0
#define OFF_WHH  (OFF_WIH + 512 * 34)
#define OFF_WOBS (OFF_WHH + 512 * 34)
#define OFF_W1   (OFF_WOBS + 512 * 10)
#define OFF_A0   (OFF_W1 + 256 * 10)
#define OFF_A1   (OFF_A0 + 32 * 68)
#define OFF_GSM  (OFF_A1 + 32 * 68)
#define OFF_BSUM (OFF_GSM + 64 * 33)
#define OFF_B1   (OFF_BSUM + 32)
#define OFF_BO   (OFF_B1 + 8)
#define SMEM_FLOATS (OFF_BO + 8)
#define SMEM_BYTES (SMEM_FLOATS * 4)

__global__ void __launch_bounds__(NTHR, 1)
maro_persistent(const float* __restrict__ data,
                const float* __restrict__ mask,
                const void*  keep,
                const float* __restrict__ W1,
                const float* __restrict__ b1,
                const float* __restrict__ Wih,
                const float* __restrict__ Whh,
                const float* __restrict__ bih,
                const float* __restrict__ bhh,
                const float* __restrict__ Wobs,
                const float* __restrict__ bobs,
                float* __restrict__ out) {
    extern __shared__ float sm[];
    float* sWih  = sm + OFF_WIH;   // [512][34]  gate cols (32) for this CTA
    float* sWhh  = sm + OFF_WHH;   // [512][34]
    float* sWobs = sm + OFF_WOBS;  // [512][10]  4 mu + 4 sigma cols
    float* sW1   = sm + OFF_W1;    // [256][10]  8 x-cols
    float* sA0   = sm + OFF_A0;    // [32][68]   A staging (double buffered)
    float* sA1   = sm + OFF_A1;
    float* gsm   = sm + OFF_GSM;   // [64][33]   gate/out exchange
    float* bsum  = sm + OFF_BSUM;  // [32]
    float* sb1   = sm + OFF_B1;    // [8]
    float* sbo   = sm + OFF_BO;    // [8]

    const int id  = blockIdx.x;
    const int tid = threadIdx.x;
    const int mt  = id >> 6;       // row half: rows mt*64 .. +63
    const int ct  = id & 63;       // column tile (hidden slice for gates / col group)
    const int m0  = mt * 64;

    // ---- load persistent weight slices into SMEM ----
    for (int idx = tid; idx < 32 * 512; idx += NTHR) {
        int c = idx >> 9, k = idx & 511;
        int gcol = (c >> 3) * HID + ct * 8 + (c & 7);   // gate-interleaved cols
        sWih[k * 34 + c] = Wih[(long)gcol * HID + k];
        sWhh[k * 34 + c] = Whh[(long)gcol * HID + k];
    }
    for (int idx = tid; idx < 8 * 512; idx += NTHR) {
        int c = idx >> 9, k = idx & 511;
        int gcol = (c < 4) ? (ct * 4 + c) : (IND + ct * 4 + (c - 4));
        sWobs[k * 10 + c] = Wobs[(long)gcol * HID + k];
    }
    for (int idx = tid; idx < 8 * 256; idx += NTHR) {
        int c = idx >> 8, k = idx & 255;
        sW1[k * 10 + c] = W1[(long)(ct * 8 + c) * IND + k];
    }
    if (tid < 32) {
        int q = tid >> 3, u = tid & 7;
        int gcol = q * HID + ct * 8 + u;
        bsum[tid] = bih[gcol] + bhh[gcol];
    }
    if (tid < 8) {
        sb1[tid] = b1[ct * 8 + tid];
        sbo[tid] = (tid < 4) ? bobs[ct * 4 + tid] : bobs[IND + ct * 4 + (tid - 4)];
    }

    // ---- init global state (distributed) ----
    int gid = id * NTHR + tid;                  // 0..32767
    for (int j = gid; j < BSZ * HID; j += NCTA * NTHR) { g_c[j] = 0.0f; g_hbuf[j] = 0.0f; }
    for (int j = gid; j < BSZ * IND; j += NCTA * NTHR) {
        int b = j >> 8, k = j & 255;
        g_mixed[j] = data[(long)b * TT * IND + k];     // mixed_0 = data[:,0] (keep[0]=True)
    }
    if (gid == 0) {
        const unsigned int* w = (const unsigned int*)keep;
        int fmt = 0;
        for (int q = 0; q < 256; q++) {
            unsigned int v = w[q];
            if (v == 0x3f800000u) { fmt = 1; break; }
            if (v > 1u)           { fmt = 2; break; }
        }
        g_kfmt = fmt;
    }

    unsigned bt = 0;
    gridbar(bt);
    const int fmt = g_kfmt;

    float lacc = 0.0f;   // per-thread loss accumulator (fixed (batch,dim) ownership)

    for (int t = 0; t < TS; t++) {
        const float* hread  = g_hbuf + (t & 1) * (BSZ * HID);
        float*       hwrite = g_hbuf + ((t + 1) & 1) * (BSZ * HID);

        // ===================== phase X: x = relu(mixed @ W1^T + b1) =====================
        {
            const int ty = tid >> 2, tx = tid & 3;   // 64 rows x 4 colpairs (8 cols)
            ull acc = 0ull;
            float4 p0, p1;
            PF(p0, p1, g_mixed, IND, 0);
            STG(sA0, p0, p1);
            __syncthreads();
            for (int cc = 0; cc < 8; cc++) {
                float* cur = (cc & 1) ? sA1 : sA0;
                if (cc < 7) PF(p0, p1, g_mixed, IND, (cc + 1) * 32);
                #pragma unroll
                for (int kk = 0; kk < 32; kk++) {
                    float av = cur[kk * 68 + ty];
                    ull bv = *(const ull*)&sW1[(cc * 32 + kk) * 10 + tx * 2];
                    fma2(acc, pk2(av, av), bv);
                }
                if (cc < 7) { float* nb = (cc & 1) ? sA0 : sA1; STG(nb, p0, p1); }
                __syncthreads();
            }
            float v0, v1; upk2(acc, v0, v1);
            v0 = fmaxf(v0 + sb1[tx * 2], 0.0f);
            v1 = fmaxf(v1 + sb1[tx * 2 + 1], 0.0f);
            *(float2*)&g_x[(m0 + ty) * HID + ct * 8 + tx * 2] = make_float2(v0, v1);
        }
        gridbar(bt);

        // ============ phase G: gates = x@Wih^T + h@Whh^T + b; LSTM update ============
        {
            const int ty = tid >> 4, tx = tid & 15;  // 16x16 -> 64 rows x 32 cols, TM=4 TN=2
            ull acc[4] = {0ull, 0ull, 0ull, 0ull};
            float4 p0, p1;
            PF(p0, p1, g_x, HID, 0);
            STG(sA0, p0, p1);
            __syncthreads();
            for (int cc = 0; cc < 32; cc++) {
                float* cur = (cc & 1) ? sA1 : sA0;
                if (cc < 31) {
                    if (cc + 1 < 16) PF(p0, p1, g_x, HID, (cc + 1) * 32);
                    else             PF(p0, p1, hread, HID, (cc + 1 - 16) * 32);
                }
                const float* W = (cc < 16) ? sWih : sWhh;
                const int kb = (cc & 15) * 32;
                #pragma unroll
                for (int kk = 0; kk < 32; kk++) {
                    float4 a4 = *(const float4*)&cur[kk * 68 + ty * 4];
                    ull bv = *(const ull*)&W[(kb + kk) * 34 + tx * 2];
                    fma2(acc[0], pk2(a4.x, a4.x), bv);
                    fma2(acc[1], pk2(a4.y, a4.y), bv);
                    fma2(acc[2], pk2(a4.z, a4.z), bv);
                    fma2(acc[3], pk2(a4.w, a4.w), bv);
                }
                if (cc < 31) { float* nb = (cc & 1) ? sA0 : sA1; STG(nb, p0, p1); }
                __syncthreads();
            }
            #pragma unroll
            for (int r = 0; r < 4; r++) {
                float v0, v1; upk2(acc[r], v0, v1);
                gsm[(ty * 4 + r) * 33 + tx * 2]     = v0;
                gsm[(ty * 4 + r) * 33 + tx * 2 + 1] = v1;
            }
            __syncthreads();
            // LSTM epilogue: 2 cells/thread
            const int r = tid >> 2, u0 = (tid & 3) * 2;
            #pragma unroll
            for (int uu = 0; uu < 2; uu++) {
                int u = u0 + uu;
                float iv = gsm[r * 33 + u]       + bsum[u];
                float fv = gsm[r * 33 + 8 + u]   + bsum[8 + u];
                float gv = gsm[r * 33 + 16 + u]  + bsum[16 + u];
                float ov = gsm[r * 33 + 24 + u]  + bsum[24 + u];
                int ci = (m0 + r) * HID + ct * 8 + u;
                float cc2 = sigf(fv) * g_c[ci] + sigf(iv) * tanhf(gv);
                g_c[ci] = cc2;
                hwrite[ci] = sigf(ov) * tanhf(cc2);
            }
        }
        gridbar(bt);

        // ====== phase O: out = h@Wobs^T + b; loss partial; mixed for next step ======
        {
            const int ty = tid >> 2, tx = tid & 3;   // 64 rows x 4 colpairs (8 cols)
            ull acc = 0ull;
            float4 p0, p1;
            PF(p0, p1, hwrite, HID, 0);
            STG(sA0, p0, p1);
            __syncthreads();
            for (int cc = 0; cc < 16; cc++) {
                float* cur = (cc & 1) ? sA1 : sA0;
                if (cc < 15) PF(p0, p1, hwrite, HID, (cc + 1) * 32);
                #pragma unroll
                for (int kk = 0; kk < 32; kk++) {
                    float av = cur[kk * 68 + ty];
                    ull bv = *(const ull*)&sWobs[(cc * 32 + kk) * 10 + tx * 2];
                    fma2(acc, pk2(av, av), bv);
                }
                if (cc < 15) { float* nb = (cc & 1) ? sA0 : sA1; STG(nb, p0, p1); }
                __syncthreads();
            }
            {
                float v0, v1; upk2(acc, v0, v1);
                gsm[ty * 9 + tx * 2]     = v0;
                gsm[ty * 9 + tx * 2 + 1] = v1;
            }
            __syncthreads();
            // loss + teacher-forcing epilogue: 1 (b,dim)/thread
            const int r = tid >> 2, dd = tid & 3;
            const int b = m0 + r;
            const int kidx = ct * 4 + dd;
            float mu = gsm[r * 9 + dd]     + sbo[dd];
            float s  = gsm[r * 9 + 4 + dd] + sbo[4 + dd];
            long di = ((long)b * TT + t) * IND + kidx;
            float dc = data[di];
            float dn = data[di + IND];
            float e = expf(-s);
            float z = (dn - dc - mu) * e;
            lacc += mask[(long)b * TT + t] * (-0.5f * z * z - s - 0.9189385332046727f);
            if (t < TS - 1) {
                int na = kidx >> 5;
                bool kp = keep_at(keep, fmt, t + 1, b, na);
                g_mixed[b * IND + kidx] = kp ? dn : (dc + mu);
            }
            __syncthreads();  // protect gsm before next step reuses it
        }
        gridbar(bt);
    }

    // ---- spill loss partials, final deterministic reduction by CTA 0 ----
    g_lp[(m0 + (tid >> 2)) * 256 + ct * 4 + (tid & 3)] = lacc;
    gridbar(bt);

    if (id == 0) {
        if (tid < BSZ) {
            int b = tid;
            float num = 0.0f;
            for (int s = 0; s < 256; s++) num += g_lp[b * 256 + s];
            float den = 0.0f;
            for (int t = 0; t < TS; t++) den += mask[(long)b * TT + t];
            gsm[tid] = -num / (den * (float)NA);
        }
        __syncthreads();
        if (tid == 0) {
            float sum = 0.0f;
            for (int i = 0; i < BSZ; i++) sum += gsm[i];
            out[0] = sum / (float)BSZ;
            g_cnt = 0;   // reset barrier counter for the next graph replay
        }
    }
}

// ---------------- launcher ----------------
extern "C" void kernel_launch(void* const* d_in, const int* in_sizes, int n_in,
                              void* d_out, int out_size) {
    const float* data = (const float*)d_in[0];
    const float* mask = (const float*)d_in[1];
    const void*  keep = d_in[2];
    const float* W1   = (const float*)d_in[3];
    const float* b1   = (const float*)d_in[4];
    const float* Wih  = (const float*)d_in[5];
    const float* Whh  = (const float*)d_in[6];
    const float* bih  = (const float*)d_in[7];
    const float* bhh  = (const float*)d_in[8];
    const float* Wobs = (const float*)d_in[9];
    const float* bobs = (const float*)d_in[10];
    float* out = (float*)d_out;

    cudaFuncSetAttribute(maro_persistent,
                         cudaFuncAttributeMaxDynamicSharedMemorySize, SMEM_BYTES);
    maro_persistent<<<NCTA, NTHR, SMEM_BYTES>>>(data, mask, keep, W1, b1, Wih, Whh,
                                                bih, bhh, Wobs, bobs, out);
}

// round 4
// speedup vs baseline: 1.1822x; 1.1822x over previous
#include <cuda_runtime.h>
#include <math.h>

// Problem constants
#define BSZ 128
#define TT  512
#define TS  511          // steps = T-1
#define NA  8
#define IND 256          // NA*OD
#define HID 512
#define NCTA 128
#define NTHR 256

typedef unsigned long long ull;

// ---------------- device scratch (no allocations allowed) ----------------
__device__ float g_x[BSZ * HID];          // relu(W1 @ mixed)
__device__ float g_hbuf[2 * BSZ * HID];   // ping-pong h
__device__ float g_c[BSZ * HID];          // cell state (CTA-owned slices)
__device__ float g_mixed[BSZ * IND];      // teacher-forced input for next step
__device__ float g_lp[BSZ * 256];         // per-thread loss partials
__device__ unsigned g_cnt = 0;            // grid barrier counter (monotonic per launch)
__device__ int g_kfmt;                    // comm_keep format: 0=i32,1=f32,2=u8

// ---------------- f32x2 helpers ----------------
__device__ __forceinline__ ull pk2(float lo, float hi) {
    ull r; asm("mov.b64 %0, {%1, %2};" : "=l"(r) : "f"(lo), "f"(hi)); return r;
}
__device__ __forceinline__ void upk2(ull v, float& lo, float& hi) {
    asm("mov.b64 {%0, %1}, %2;" : "=f"(lo), "=f"(hi) : "l"(v));
}
__device__ __forceinline__ void fma2(ull& acc, ull a, ull b) {
    asm("fma.rn.f32x2 %0, %1, %2, %0;" : "+l"(acc) : "l"(a), "l"(b));
}
__device__ __forceinline__ float sigf(float x) { return 1.0f / (1.0f + __expf(-x)); }
__device__ __forceinline__ float tanhfast(float x) {
    float r; asm("tanh.approx.f32 %0, %1;" : "=f"(r) : "f"(x)); return r;
}

__device__ __forceinline__ bool keep_at(const void* keep, int fmt, int step, int b, int na) {
    long idx = ((long)step * BSZ + b) * NA + na;
    if (fmt == 0) return ((const int*)keep)[idx] != 0;
    if (fmt == 1) return ((const float*)keep)[idx] != 0.0f;
    return ((const unsigned char*)keep)[idx] != 0;
}

// ---------------- split grid barrier (monotonic counter) ----------------
#define B_ARRIVE() do {                                            \
    __syncthreads();                                               \
    if (tid == 0) { __threadfence(); atomicAdd(&g_cnt, 1u); }      \
    nb++;                                                          \
} while (0)

#define B_WAIT() do {                                              \
    if (tid == 0) {                                                \
        unsigned _t = nb * NCTA;                                   \
        while (*(volatile unsigned*)&g_cnt < _t) { }               \
        __threadfence();                                           \
    }                                                              \
    __syncthreads();                                               \
} while (0)

// ---------------- staging: 64 rows x 32 k chunk, transposed to [k][row] --------
#define PF(P0, P1, SRC, RS, CB) do {                                             \
    int _l0 = tid, _l1 = tid + 256;                                              \
    P0 = *(const float4*)&(SRC)[(m0 + (_l0 >> 3)) * (RS) + (CB) + ((_l0 & 7) << 2)]; \
    P1 = *(const float4*)&(SRC)[(m0 + (_l1 >> 3)) * (RS) + (CB) + ((_l1 & 7) << 2)]; \
} while (0)

#define STG(BUF, P0, P1) do {                                                    \
    int _l0 = tid, _l1 = tid + 256;                                              \
    float* _d0 = &(BUF)[((_l0 & 7) << 2) * 68 + (_l0 >> 3)];                     \
    _d0[0] = P0.x; _d0[68] = P0.y; _d0[136] = P0.z; _d0[204] = P0.w;             \
    float* _d1 = &(BUF)[((_l1 & 7) << 2) * 68 + (_l1 >> 3)];                     \
    _d1[0] = P1.x; _d1[68] = P1.y; _d1[136] = P1.z; _d1[204] = P1.w;             \
} while (0)

// gates GEMM chunk block: accumulate src[m0..+63, KB..KB+NCH*32) @ W-cols into acc[4]
#define GEMM_G(SRC, KB, NCH, WBASE) do {                                         \
    float4 p0, p1;                                                               \
    PF(p0, p1, SRC, HID, (KB));                                                  \
    STG(sA0, p0, p1);                                                            \
    __syncthreads();                                                             \
    for (int cc = 0; cc < (NCH); cc++) {                                         \
        float* cur = (cc & 1) ? sA1 : sA0;                                       \
        if (cc < (NCH) - 1) PF(p0, p1, SRC, HID, (KB) + (cc + 1) * 32);          \
        const float* Wc = (WBASE) + ((KB) + cc * 32) * 34;                       \
        _Pragma("unroll")                                                        \
        for (int kk = 0; kk < 32; kk++) {                                        \
            float4 a4 = *(const float4*)&cur[kk * 68 + gty * 4];                 \
            ull bv = *(const ull*)&Wc[kk * 34 + gtx * 2];                        \
            fma2(acc[0], pk2(a4.x, a4.x), bv);                                   \
            fma2(acc[1], pk2(a4.y, a4.y), bv);                                   \
            fma2(acc[2], pk2(a4.z, a4.z), bv);                                   \
            fma2(acc[3], pk2(a4.w, a4.w), bv);                                   \
        }                                                                        \
        if (cc < (NCH) - 1) { float* nbuf = (cc & 1) ? sA0 : sA1; STG(nbuf, p0, p1); } \
        __syncthreads();                                                         \
    }                                                                            \
} while (0)

// SMEM layout (floats)
#define OFF_WIH  0
#define OFF_WHH  (OFF_WIH + 512 * 34)
#define OFF_WOBS (OFF_WHH + 512 * 34)
#define OFF_W1   (OFF_WOBS + 512 * 10)
#define OFF_A0   (OFF_W1 + 256 * 10)
#define OFF_A1   (OFF_A0 + 32 * 68)
#define OFF_GSM  (OFF_A1 + 32 * 68)
#define OFF_BSUM (OFF_GSM + 64 * 33)
#define OFF_B1   (OFF_BSUM + 32)
#define OFF_BO   (OFF_B1 + 8)
#define SMEM_FLOATS (OFF_BO + 8)
#define SMEM_BYTES (SMEM_FLOATS * 4)

__global__ void __launch_bounds__(NTHR, 1)
maro_persistent(const float* __restrict__ data,
                const float* __restrict__ mask,
                const void*  keep,
                const float* __restrict__ W1,
                const float* __restrict__ b1,
                const float* __restrict__ Wih,
                const float* __restrict__ Whh,
                const float* __restrict__ bih,
                const float* __restrict__ bhh,
                const float* __restrict__ Wobs,
                const float* __restrict__ bobs,
                float* __restrict__ out) {
    extern __shared__ float sm[];
    float* sWih  = sm + OFF_WIH;   // [512][34]  gate cols (32) for this CTA
    float* sWhh  = sm + OFF_WHH;   // [512][34]
    float* sWobs = sm + OFF_WOBS;  // [512][10]  4 mu + 4 sigma cols
    float* sW1   = sm + OFF_W1;    // [256][10]  8 x-cols
    float* sA0   = sm + OFF_A0;    // [32][68]   A staging (double buffered)
    float* sA1   = sm + OFF_A1;
    float* gsm   = sm + OFF_GSM;   // [64][33]   gate/out exchange
    float* bsum  = sm + OFF_BSUM;  // [32]
    float* sb1   = sm + OFF_B1;    // [8]
    float* sbo   = sm + OFF_BO;    // [8]

    const int id  = blockIdx.x;
    const int tid = threadIdx.x;
    const int mt  = id >> 6;       // row half
    const int ct  = id & 63;       // column tile
    const int m0  = mt * 64;
    const int gty = tid >> 4, gtx = tid & 15;   // gates mapping: 16x16, TM=4 TN=2

    // ---- load persistent weight slices into SMEM ----
    for (int idx = tid; idx < 32 * 512; idx += NTHR) {
        int c = idx >> 9, k = idx & 511;
        int gcol = (c >> 3) * HID + ct * 8 + (c & 7);   // gate-interleaved cols
        sWih[k * 34 + c] = Wih[(long)gcol * HID + k];
        sWhh[k * 34 + c] = Whh[(long)gcol * HID + k];
    }
    for (int idx = tid; idx < 8 * 512; idx += NTHR) {
        int c = idx >> 9, k = idx & 511;
        int gcol = (c < 4) ? (ct * 4 + c) : (IND + ct * 4 + (c - 4));
        sWobs[k * 10 + c] = Wobs[(long)gcol * HID + k];
    }
    for (int idx = tid; idx < 8 * 256; idx += NTHR) {
        int c = idx >> 8, k = idx & 255;
        sW1[k * 10 + c] = W1[(long)(ct * 8 + c) * IND + k];
    }
    if (tid < 32) {
        int q = tid >> 3, u = tid & 7;
        int gcol = q * HID + ct * 8 + u;
        bsum[tid] = bih[gcol] + bhh[gcol];
    }
    if (tid < 8) {
        sb1[tid] = b1[ct * 8 + tid];
        sbo[tid] = (tid < 4) ? bobs[ct * 4 + tid] : bobs[IND + ct * 4 + (tid - 4)];
    }

    // ---- init global state (distributed) ----
    int gid = id * NTHR + tid;
    for (int j = gid; j < BSZ * HID; j += NCTA * NTHR) { g_c[j] = 0.0f; g_hbuf[j] = 0.0f; }
    for (int j = gid; j < BSZ * IND; j += NCTA * NTHR) {
        int b = j >> 8, k = j & 255;
        g_mixed[j] = data[(long)b * TT * IND + k];     // mixed_0 = data[:,0]
    }
    if (gid == 0) {
        const unsigned int* w = (const unsigned int*)keep;
        int fmt = 0;
        for (int q = 0; q < 256; q++) {
            unsigned int v = w[q];
            if (v == 0x3f800000u) { fmt = 1; break; }
            if (v > 1u)           { fmt = 2; break; }
        }
        g_kfmt = fmt;
    }

    unsigned nb = 0;
    B_ARRIVE(); B_WAIT();
    const int fmt = g_kfmt;

    float lacc = 0.0f;   // per-thread loss accumulator

    for (int t = 0; t < TS; t++) {
        const float* hread  = g_hbuf + (t & 1) * (BSZ * HID);
        float*       hwrite = g_hbuf + ((t + 1) & 1) * (BSZ * HID);

        ull acc[4] = {0ull, 0ull, 0ull, 0ull};   // gates accumulators

        // ---- G-hh first half: overlaps the O-barrier of step t-1 ----
        GEMM_G(hread, 0, 8, sWhh);
        if (t > 0) B_WAIT();                     // wait O(t-1): g_mixed ready

        // ===================== phase X: x = relu(mixed @ W1^T + b1) ===============
        {
            const int ty = tid >> 2, tx = tid & 3;
            ull xacc = 0ull;
            float4 p0, p1;
            PF(p0, p1, g_mixed, IND, 0);
            STG(sA0, p0, p1);
            __syncthreads();
            for (int cc = 0; cc < 8; cc++) {
                float* cur = (cc & 1) ? sA1 : sA0;
                if (cc < 7) PF(p0, p1, g_mixed, IND, (cc + 1) * 32);
                #pragma unroll
                for (int kk = 0; kk < 32; kk++) {
                    float av = cur[kk * 68 + ty];
                    ull bv = *(const ull*)&sW1[(cc * 32 + kk) * 10 + tx * 2];
                    fma2(xacc, pk2(av, av), bv);
                }
                if (cc < 7) { float* nbuf = (cc & 1) ? sA0 : sA1; STG(nbuf, p0, p1); }
                __syncthreads();
            }
            float v0, v1; upk2(xacc, v0, v1);
            v0 = fmaxf(v0 + sb1[tx * 2], 0.0f);
            v1 = fmaxf(v1 + sb1[tx * 2 + 1], 0.0f);
            *(float2*)&g_x[(m0 + ty) * HID + ct * 8 + tx * 2] = make_float2(v0, v1);
        }
        B_ARRIVE();                               // arrive X

        // ---- G-hh second half: overlaps the X barrier ----
        GEMM_G(hread, 256, 8, sWhh);
        B_WAIT();                                 // wait X: g_x ready

        // ---- G-ih + LSTM epilogue ----
        GEMM_G(g_x, 0, 16, sWih);
        #pragma unroll
        for (int r = 0; r < 4; r++) {
            float v0, v1; upk2(acc[r], v0, v1);
            gsm[(gty * 4 + r) * 33 + gtx * 2]     = v0;
            gsm[(gty * 4 + r) * 33 + gtx * 2 + 1] = v1;
        }
        __syncthreads();
        {
            const int r = tid >> 2, u0 = (tid & 3) * 2;
            #pragma unroll
            for (int uu = 0; uu < 2; uu++) {
                int u = u0 + uu;
                float iv = gsm[r * 33 + u]       + bsum[u];
                float fv = gsm[r * 33 + 8 + u]   + bsum[8 + u];
                float gv = gsm[r * 33 + 16 + u]  + bsum[16 + u];
                float ov = gsm[r * 33 + 24 + u]  + bsum[24 + u];
                int ci = (m0 + r) * HID + ct * 8 + u;
                float cc2 = sigf(fv) * g_c[ci] + sigf(iv) * tanhfast(gv);
                g_c[ci] = cc2;
                hwrite[ci] = sigf(ov) * tanhfast(cc2);
            }
        }
        B_ARRIVE();                               // arrive G

        // ---- hoist loss-epilogue globals: overlaps the G barrier ----
        const int er = tid >> 2, edd = tid & 3;
        const int eb = m0 + er;
        const int kidx = ct * 4 + edd;
        long di = ((long)eb * TT + t) * IND + kidx;
        float dc = data[di];
        float dn = data[di + IND];
        float mv = mask[(long)eb * TT + t];
        bool kp = false;
        if (t < TS - 1) kp = keep_at(keep, fmt, t + 1, eb, kidx >> 5);

        B_WAIT();                                 // wait G: hwrite ready

        // ====== phase O: out = h@Wobs^T + b; loss; mixed for next step ======
        {
            const int ty = tid >> 2, tx = tid & 3;
            ull oacc = 0ull;
            float4 p0, p1;
            PF(p0, p1, hwrite, HID, 0);
            STG(sA0, p0, p1);
            __syncthreads();
            for (int cc = 0; cc < 16; cc++) {
                float* cur = (cc & 1) ? sA1 : sA0;
                if (cc < 15) PF(p0, p1, hwrite, HID, (cc + 1) * 32);
                #pragma unroll
                for (int kk = 0; kk < 32; kk++) {
                    float av = cur[kk * 68 + ty];
                    ull bv = *(const ull*)&sWobs[(cc * 32 + kk) * 10 + tx * 2];
                    fma2(oacc, pk2(av, av), bv);
                }
                if (cc < 15) { float* nbuf = (cc & 1) ? sA0 : sA1; STG(nbuf, p0, p1); }
                __syncthreads();
            }
            float v0, v1; upk2(oacc, v0, v1);
            gsm[ty * 9 + tx * 2]     = v0;
            gsm[ty * 9 + tx * 2 + 1] = v1;
            __syncthreads();
            // loss + teacher-forcing epilogue
            float mu = gsm[er * 9 + edd]     + sbo[edd];
            float s  = gsm[er * 9 + 4 + edd] + sbo[4 + edd];
            float e = __expf(-s);
            float z = (dn - dc - mu) * e;
            lacc += mv * (-0.5f * z * z - s - 0.9189385332046727f);
            if (t < TS - 1) g_mixed[eb * IND + kidx] = kp ? dn : (dc + mu);
        }
        B_ARRIVE();                               // arrive O (waited next iter)
    }

    // ---- spill loss partials; non-zero CTAs exit; CTA0 reduces + resets ----
    g_lp[(m0 + (tid >> 2)) * 256 + ct * 4 + (tid & 3)] = lacc;
    B_ARRIVE();                                   // final arrive (no global wait for id!=0)
    if (id != 0) return;

    if (tid == 0) {
        unsigned tgt = nb * NCTA;
        while (*(volatile unsigned*)&g_cnt < tgt) { }
        __threadfence();
    }
    __syncthreads();

    if (tid < BSZ) {
        int b = tid;
        float num = 0.0f;
        for (int s = 0; s < 256; s++) num += g_lp[b * 256 + s];
        float den = 0.0f;
        for (int t = 0; t < TS; t++) den += mask[(long)b * TT + t];
        gsm[tid] = -num / (den * (float)NA);
    }
    __syncthreads();
    if (tid == 0) {
        float sum = 0.0f;
        for (int i = 0; i < BSZ; i++) sum += gsm[i];
        out[0] = sum / (float)BSZ;
        g_cnt = 0;   // safe: all other CTAs have passed every wait and arrived
    }
}

// ---------------- launcher ----------------
extern "C" void kernel_launch(void* const* d_in, const int* in_sizes, int n_in,
                              void* d_out, int out_size) {
    const float* data = (const float*)d_in[0];
    const float* mask = (const float*)d_in[1];
    const void*  keep = d_in[2];
    const float* W1   = (const float*)d_in[3];
    const float* b1   = (const float*)d_in[4];
    const float* Wih  = (const float*)d_in[5];
    const float* Whh  = (const float*)d_in[6];
    const float* bih  = (const float*)d_in[7];
    const float* bhh  = (const float*)d_in[8];
    const float* Wobs = (const float*)d_in[9];
    const float* bobs = (const float*)d_in[10];
    float* out = (float*)d_out;

    cudaFuncSetAttribute(maro_persistent,
                         cudaFuncAttributeMaxDynamicSharedMemorySize, SMEM_BYTES);
    maro_persistent<<<NCTA, NTHR, SMEM_BYTES>>>(data, mask, keep, W1, b1, Wih, Whh,
                                                bih, bhh, Wobs, bobs, out);
}